// round 13
// baseline (speedup 1.0000x reference)
#include <cuda_runtime.h>
#include <cuda_bf16.h>
#include <cuda_fp16.h>
#include <cstdint>

// ROIAlign, OUT=15x15, SCALE=1/16, SR=2
// x: [2,256,64,64] f32; boxes: [512,4] f32; batch_idx: [512] i32
// out: [512,256,15,15] f32
//
// v8: SYNC-FREE one-phase gather. fp16 channels-last scratch (4.2MB, L2-resident).
// Thread = output bin; computes its own <=3x3 deduped corner lists in registers,
// gathers uint4 (8 half = 8 ch) per corner directly from g_xt, fp32-accumulates
// 32 channels, coalesced scalar stores. No smem, no __syncthreads in roi path.

#define HH 64
#define WW 64
#define CC 256
#define OUT_HW 15
#define NBOX 512
#define NCHUNK 8                         // 32 channels per chunk

// channels-last fp16 scratch: [2,64,64,256] = 4.2MB
__device__ __half g_xt[2 * HH * WW * CC];

// ---------------------------------------------------------------------------
// Transpose [B,C,H*W] f32 -> [B,H*W,C] f16 via 32x32 smem tiles
// ---------------------------------------------------------------------------
__global__ __launch_bounds__(256) void transpose_kernel(const float* __restrict__ x) {
    __shared__ float tile[32][33];
    int b   = blockIdx.z;
    int hw0 = blockIdx.x * 32;
    int c0  = blockIdx.y * 32;
    const float* src = x + ((size_t)b * CC) * (HH * WW);
    #pragma unroll
    for (int i = threadIdx.y; i < 32; i += 8)
        tile[i][threadIdx.x] = src[(size_t)(c0 + i) * (HH * WW) + hw0 + threadIdx.x];
    __syncthreads();
    __half* dst = g_xt + (size_t)b * (HH * WW) * CC;
    #pragma unroll
    for (int i = threadIdx.y; i < 32; i += 8)
        dst[(size_t)(hw0 + i) * CC + c0 + threadIdx.x] = __float2half(tile[threadIdx.x][i]);
}

// ---------------------------------------------------------------------------
// Axis corner-list builder (dedup 2 subsamples -> <=3 corners). v = valid*0.5.
// Returns absolute (clamped) indices.
// ---------------------------------------------------------------------------
__device__ __forceinline__ void axis_bin(float a1, float bin, int bin_i,
                                         int size, int* o_idx, float* o_wt, int* o_n) {
    int   idx[3];
    float wt[3];
    int   cnt = 0;
    #pragma unroll
    for (int s = 0; s < 2; s++) {
        float p = a1 + ((float)(bin_i * 2 + s) + 0.5f) * 0.5f * bin;
        const float v = (p >= -1.0f && p <= (float)size) ? 0.5f : 0.0f;
        p = fminf(fmaxf(p, 0.0f), (float)(size - 1));
        int lo = (int)floorf(p);
        if (lo > size - 1) lo = size - 1;
        const int   hi = min(lo + 1, size - 1);
        const float f  = p - (float)lo;
        int   ci[2] = { lo, hi };
        float cw[2] = { (1.0f - f) * v, f * v };
        #pragma unroll
        for (int k = 0; k < 2; k++) {
            int m;
            for (m = 0; m < cnt; m++)
                if (idx[m] == ci[k]) { wt[m] += cw[k]; break; }
            if (m == cnt && cnt < 3) { idx[cnt] = ci[k]; wt[cnt] = cw[k]; cnt++; }
        }
    }
    *o_n = cnt;
    for (int m = 0; m < cnt; m++) { o_idx[m] = idx[m]; o_wt[m] = wt[m]; }
}

// ---------------------------------------------------------------------------
// ROI kernel: grid (8 chunk, 512 box), 256 threads, thread = bin, NO syncs.
// ---------------------------------------------------------------------------
__global__ __launch_bounds__(256) void roi_kernel(const float* __restrict__ boxes,
                                                  const int* __restrict__ batch_idx,
                                                  float* __restrict__ out) {
    const int chunk = blockIdx.x;
    const int n     = blockIdx.y;
    const int tid   = threadIdx.x;

    if (tid >= OUT_HW * OUT_HW) return;

    const int h = tid / OUT_HW;
    const int w = tid - h * OUT_HW;

    // ---- box geometry (broadcast loads) ----
    const float bx1 = boxes[n * 4 + 0] * 0.0625f;
    const float by1 = boxes[n * 4 + 1] * 0.0625f;
    const float bx2 = boxes[n * 4 + 2] * 0.0625f;
    const float by2 = boxes[n * 4 + 3] * 0.0625f;
    const float bin_w = fmaxf(bx2 - bx1, 1.0f) * (1.0f / OUT_HW);
    const float bin_h = fmaxf(by2 - by1, 1.0f) * (1.0f / OUT_HW);
    const int   b     = batch_idx[n];

    // ---- per-thread corner lists (registers only) ----
    int   xo[3]; float xw[3]; int xn;
    int   yo[3]; float yw[3]; int yn;
    axis_bin(bx1, bin_w, w, WW, xo, xw, &xn);
    axis_bin(by1, bin_h, h, HH, yo, yw, &yn);

    const __half* base = g_xt + (size_t)b * (HH * WW * CC) + chunk * 32;

    // 32 channel accumulators as 16 float2 (channel c = q*8 + 2k (+1))
    float2 acc[16];
    #pragma unroll
    for (int k = 0; k < 16; k++) acc[k] = make_float2(0.f, 0.f);

    #pragma unroll
    for (int yi = 0; yi < 3; yi++) {
        if (yi < yn) {
            const int   ro = yo[yi] * WW;
            const float gy = yw[yi];
            #pragma unroll
            for (int xi = 0; xi < 3; xi++) {
                if (xi < xn) {
                    const float g = gy * xw[xi];
                    const __half* p = base + (size_t)(ro + xo[xi]) * CC;
                    #pragma unroll
                    for (int q = 0; q < 4; q++) {
                        const uint4 u = *reinterpret_cast<const uint4*>(p + q * 8);
                        const __half2* hp = reinterpret_cast<const __half2*>(&u);
                        #pragma unroll
                        for (int k = 0; k < 4; k++) {
                            const float2 f = __half22float2(hp[k]);
                            acc[q * 4 + k].x = fmaf(g, f.x, acc[q * 4 + k].x);
                            acc[q * 4 + k].y = fmaf(g, f.y, acc[q * 4 + k].y);
                        }
                    }
                }
            }
        }
    }

    // out[n, c, h, w]: channel c = chunk*32 + q*8 + 2k(+1); contiguous warp stores.
    float* obase = out + ((size_t)n * CC + chunk * 32) * (OUT_HW * OUT_HW) + tid;
    const int S = OUT_HW * OUT_HW;
    #pragma unroll
    for (int k = 0; k < 16; k++) {
        obase[(2 * k) * S]     = acc[k].x;
        obase[(2 * k + 1) * S] = acc[k].y;
    }
}

// ---------------------------------------------------------------------------
extern "C" void kernel_launch(void* const* d_in, const int* in_sizes, int n_in,
                              void* d_out, int out_size) {
    const float* x     = (const float*)d_in[0];
    const float* boxes = (const float*)d_in[1];
    const int*   bidx  = (const int*)d_in[2];
    float*       out   = (float*)d_out;

    (void)in_sizes; (void)n_in; (void)out_size;

    dim3 tb(32, 8);
    dim3 tg((HH * WW) / 32, CC / 32, 2);
    transpose_kernel<<<tg, tb>>>(x);

    dim3 rg(NCHUNK, NBOX);
    roi_kernel<<<rg, 256>>>(boxes, bidx, out);
}